// round 1
// baseline (speedup 1.0000x reference)
#include <cuda_runtime.h>
#include <cstdint>

#define NN 50000
#define EE 800000

// ---------------- static device scratch (no runtime alloc allowed) ----------
__device__ float g_bufA[(size_t)NN * 512];
__device__ float g_bufB[(size_t)NN * 512];
__device__ float g_agg [(size_t)NN * 256];
__device__ int   g_deg[NN];
__device__ float g_deg_inv[NN];
__device__ int   g_row_off[NN + 1];
__device__ int   g_fill[NN];
__device__ int   g_csr_src[EE];

// ---------------- graph build ----------------------------------------------
__global__ void k_zero_deg() {
    int i = blockIdx.x * blockDim.x + threadIdx.x;
    if (i < NN) g_deg[i] = 0;
}

__global__ void k_count_deg(const int* __restrict__ dst) {
    int e = blockIdx.x * blockDim.x + threadIdx.x;
    if (e < EE) atomicAdd(&g_deg[dst[e]], 1);
}

// single-block exclusive scan over g_deg -> g_row_off / g_fill, plus deg_inv
__global__ void k_scan_deg() {
    __shared__ int sh[1024];
    __shared__ int carry;
    int t = threadIdx.x;
    if (t == 0) carry = 0;
    __syncthreads();
    for (int base = 0; base < NN; base += 1024) {
        int i = base + t;
        int v = (i < NN) ? g_deg[i] : 0;
        sh[t] = v;
        __syncthreads();
        // Hillis-Steele inclusive scan
        #pragma unroll
        for (int off = 1; off < 1024; off <<= 1) {
            int tmp = (t >= off) ? sh[t - off] : 0;
            __syncthreads();
            sh[t] += tmp;
            __syncthreads();
        }
        int incl  = sh[t];
        int total = sh[1023];
        if (i < NN) {
            int excl = carry + incl - v;
            g_row_off[i] = excl;
            g_fill[i]    = excl;
            g_deg_inv[i] = 1.0f / fmaxf((float)v, 1.0f);
        }
        __syncthreads();
        if (t == 0) carry += total;
        __syncthreads();
    }
    if (t == 0) g_row_off[NN] = EE;
}

__global__ void k_fill_csr(const int* __restrict__ src, const int* __restrict__ dst) {
    int e = blockIdx.x * blockDim.x + threadIdx.x;
    if (e < EE) {
        int p = atomicAdd(&g_fill[dst[e]], 1);
        g_csr_src[p] = src[e];
    }
}

// ---------------- aggregation: agg[n,:] = deg_inv[n] * sum_{e in row n} h[src_e,:]
__global__ void k_aggregate(const float* __restrict__ h, float* __restrict__ agg, int din) {
    int n = blockIdx.x;
    int k = threadIdx.x;        // blockDim.x == din
    int s = g_row_off[n];
    int e1 = g_row_off[n + 1];
    float acc = 0.0f;
    for (int e = s; e < e1; e++) {
        int srcn = g_csr_src[e];
        acc += h[(size_t)srcn * din + k];
    }
    agg[(size_t)n * din + k] = acc * g_deg_inv[n];
}

// ---------------- fused SAGE gemm: C = relu([agg|h] @ [Wl|Wr]^T + b) --------
// K = 2*din (din multiple of 16), dout multiple of 64. BM=BN=64, BK=16.
#define BM 64
#define BN 64
#define BK 16

__global__ __launch_bounds__(256)
void k_gemm_sage(const float* __restrict__ A0,   // agg  [NN, din]
                 const float* __restrict__ A1,   // h    [NN, din]
                 const float* __restrict__ W0,   // Wl   [dout, din]
                 const float* __restrict__ W1,   // Wr   [dout, din]
                 const float* __restrict__ bias, // [dout]
                 float* __restrict__ C,          // [NN, dout]
                 int din, int dout)
{
    __shared__ float As[BK][BM + 1];
    __shared__ float Bs[BK][BN + 1];

    int tid = threadIdx.x;
    int tx = tid & 15;
    int ty = tid >> 4;
    int rowBase = blockIdx.x * BM;
    int colBase = blockIdx.y * BN;

    int lr = tid >> 2;          // 0..63  tile row
    int lc = (tid & 3) * 4;     // 0,4,8,12 col group

    float acc[4][4] = {};
    const int K = 2 * din;

    for (int k0 = 0; k0 < K; k0 += BK) {
        const float* Abase;
        const float* Wbase;
        int kk;
        if (k0 < din) { Abase = A0; Wbase = W0; kk = k0; }
        else          { Abase = A1; Wbase = W1; kk = k0 - din; }

        // A tile
        {
            int gr = rowBase + lr;
            float4 av = make_float4(0.f, 0.f, 0.f, 0.f);
            if (gr < NN)
                av = *reinterpret_cast<const float4*>(&Abase[(size_t)gr * din + kk + lc]);
            As[lc + 0][lr] = av.x;
            As[lc + 1][lr] = av.y;
            As[lc + 2][lr] = av.z;
            As[lc + 3][lr] = av.w;
        }
        // B tile (weights, no row guard: dout multiple of 64)
        {
            int gj = colBase + lr;
            float4 bv = *reinterpret_cast<const float4*>(&Wbase[(size_t)gj * din + kk + lc]);
            Bs[lc + 0][lr] = bv.x;
            Bs[lc + 1][lr] = bv.y;
            Bs[lc + 2][lr] = bv.z;
            Bs[lc + 3][lr] = bv.w;
        }
        __syncthreads();

        #pragma unroll
        for (int k = 0; k < BK; k++) {
            float a[4], b[4];
            #pragma unroll
            for (int i = 0; i < 4; i++) a[i] = As[k][ty + i * 16];
            #pragma unroll
            for (int j = 0; j < 4; j++) b[j] = Bs[k][tx + j * 16];
            #pragma unroll
            for (int i = 0; i < 4; i++)
                #pragma unroll
                for (int j = 0; j < 4; j++)
                    acc[i][j] += a[i] * b[j];
        }
        __syncthreads();
    }

    #pragma unroll
    for (int i = 0; i < 4; i++) {
        int r = rowBase + ty + i * 16;
        if (r >= NN) continue;
        #pragma unroll
        for (int j = 0; j < 4; j++) {
            int c = colBase + tx + j * 16;
            float v = acc[i][j] + bias[c];
            v = fmaxf(v, 0.0f);
            C[(size_t)r * dout + c] = v;
        }
    }
}

// ---------------- head: logits = h @ Wout^T + bout; softmax -----------------
__global__ void k_head(const float* __restrict__ h, const float* __restrict__ Wout,
                       const float* __restrict__ bout, float* __restrict__ out) {
    int gwarp = (blockIdx.x * blockDim.x + threadIdx.x) >> 5;
    int lane  = threadIdx.x & 31;
    if (gwarp >= NN) return;
    const float* hr = h + (size_t)gwarp * 512;
    float s[4] = {0.f, 0.f, 0.f, 0.f};
    for (int i = lane; i < 512; i += 32) {
        float hv = hr[i];
        #pragma unroll
        for (int c = 0; c < 4; c++) s[c] += hv * Wout[c * 512 + i];
    }
    #pragma unroll
    for (int off = 16; off > 0; off >>= 1)
        #pragma unroll
        for (int c = 0; c < 4; c++)
            s[c] += __shfl_xor_sync(0xFFFFFFFF, s[c], off);
    if (lane == 0) {
        float l[4];
        float m = -1e30f;
        #pragma unroll
        for (int c = 0; c < 4; c++) { l[c] = s[c] + bout[c]; m = fmaxf(m, l[c]); }
        float den = 0.f;
        #pragma unroll
        for (int c = 0; c < 4; c++) { l[c] = __expf(l[c] - m); den += l[c]; }
        float inv = 1.0f / den;
        #pragma unroll
        for (int c = 0; c < 4; c++) out[(size_t)gwarp * 4 + c] = l[c] * inv;
    }
}

// ---------------- driver -----------------------------------------------------
extern "C" void kernel_launch(void* const* d_in, const int* in_sizes, int n_in,
                              void* d_out, int out_size)
{
    const float* x    = (const float*)d_in[0];
    const float* Wl[5] = {(const float*)d_in[1],  (const float*)d_in[4],
                          (const float*)d_in[7],  (const float*)d_in[10],
                          (const float*)d_in[13]};
    const float* bl[5] = {(const float*)d_in[2],  (const float*)d_in[5],
                          (const float*)d_in[8],  (const float*)d_in[11],
                          (const float*)d_in[14]};
    const float* Wr[5] = {(const float*)d_in[3],  (const float*)d_in[6],
                          (const float*)d_in[9],  (const float*)d_in[12],
                          (const float*)d_in[15]};
    const float* Wout = (const float*)d_in[16];
    const float* bout = (const float*)d_in[17];
    const int*   ei   = (const int*)d_in[18];
    const int* src = ei;
    const int* dst = ei + EE;

    float *bufA, *bufB, *aggp;
    cudaGetSymbolAddress((void**)&bufA, g_bufA);
    cudaGetSymbolAddress((void**)&bufB, g_bufB);
    cudaGetSymbolAddress((void**)&aggp, g_agg);

    // 1. build CSR by dst
    k_zero_deg<<<(NN + 255) / 256, 256>>>();
    k_count_deg<<<(EE + 255) / 256, 256>>>(dst);
    k_scan_deg<<<1, 1024>>>();
    k_fill_csr<<<(EE + 255) / 256, 256>>>(src, dst);

    // 2. layers
    const int dins[5]  = {128, 128, 64, 128, 256};
    const int douts[5] = {128,  64, 128, 256, 512};
    const float* hcur = x;
    float* bufs[2] = {bufA, bufB};
    for (int i = 0; i < 5; i++) {
        int din = dins[i], dout = douts[i];
        k_aggregate<<<NN, din>>>(hcur, aggp, din);
        float* hnext = bufs[i & 1];
        dim3 grid((NN + BM - 1) / BM, dout / BN);
        k_gemm_sage<<<grid, 256>>>(aggp, hcur, Wl[i], Wr[i], bl[i], hnext, din, dout);
        hcur = hnext;
    }

    // 3. head + softmax (hcur == bufA, 512-wide)
    k_head<<<(NN * 32 + 255) / 256, 256>>>(hcur, Wout, bout, (float*)d_out);
}